// round 8
// baseline (speedup 1.0000x reference)
#include <cuda_runtime.h>
#include <cstdint>

// TinyGRU: B=4096 sequences, S=2048 steps, I=3, H=4, O=2.
// Strategy: 4 threads per batch (one per hidden unit). Each thread computes
// the r/z/n gates of its unit; the full hidden vector is replicated across
// the 4 threads via shfl after every step. Inputs/outputs staged through
// shared memory in 16-step tiles for coalesced global traffic.

#define Bq   4096
#define Sq   2048
#define Iq   3
#define Hq   4
#define Oq   2
#define TILE 16
#define BPC  32          // batches per CTA
#define THR  128         // threads per CTA (4 per batch)
#define NTILE (Sq / TILE)

#define SIN_STRIDE  52   // 48 floats data + pad (bank-conflict free, 16B aligned rows)
#define SOUT_STRIDE 36   // 32 floats data + pad

__device__ __forceinline__ float ex2f(float x) {
    float y; asm("ex2.approx.f32 %0, %1;" : "=f"(y) : "f"(x)); return y;
}
__device__ __forceinline__ float rcpf(float x) {
    float y; asm("rcp.approx.f32 %0, %1;" : "=f"(y) : "f"(x)); return y;
}
// sigmoid(x) = 1 / (1 + exp(-x)) = 1 / (1 + 2^(-x*log2e))
__device__ __forceinline__ float sigmoid_fast(float x) {
    return rcpf(fmaf(0.0f, x, 1.0f) + ex2f(-1.4426950408889634f * x));
}
// tanh(x) = 2*sigmoid(2x) - 1
__device__ __forceinline__ float tanh_fast(float x) {
    return fmaf(2.0f, rcpf(1.0f + ex2f(-2.8853900817779268f * x)), -1.0f);
}

__global__ void __launch_bounds__(THR, 1) gru_kernel(
    const float* __restrict__ inputs,  // [B, S, I]
    const float* __restrict__ W_ih,    // [3H, I]
    const float* __restrict__ W_hh,    // [3H, H]
    const float* __restrict__ b_ih,    // [3H]
    const float* __restrict__ b_hh,    // [3H]
    const float* __restrict__ W_ro,    // [O, H]
    const float* __restrict__ b_ro,    // [O]
    const float* __restrict__ h0,      // [1, H]
    float* __restrict__ out,           // [B*S*O] (+ optional [B*H] h_final)
    int write_hfinal)
{
    __shared__ float s_in[BPC * SIN_STRIDE];
    __shared__ float s_out[BPC * SOUT_STRIDE];

    const int tid  = threadIdx.x;
    const int lane = tid & 31;
    const int j    = tid & 3;         // hidden unit owned by this thread
    const int bloc = tid >> 2;        // local batch 0..31
    const int b    = blockIdx.x * BPC + bloc;
    const unsigned gbase = (unsigned)(lane & ~3);

    // ---- load weights into registers (rows [r, z, n] = [0:H, H:2H, 2H:3H]) ----
    float wx[3][3], wh[3][4];
#pragma unroll
    for (int g = 0; g < 3; g++) {
        const int row = g * Hq + j;
#pragma unroll
        for (int i = 0; i < 3; i++) wx[g][i] = W_ih[row * Iq + i];
#pragma unroll
        for (int m = 0; m < 4; m++) wh[g][m] = W_hh[row * Hq + m];
    }
    const float br  = b_ih[j]          + b_hh[j];
    const float bz  = b_ih[Hq + j]     + b_hh[Hq + j];
    const float bxn = b_ih[2 * Hq + j];
    const float bhn = b_hh[2 * Hq + j];
    const int jo = (j < 2) ? j : 0;
    float wro[4];
#pragma unroll
    for (int m = 0; m < 4; m++) wro[m] = W_ro[jo * Hq + m];
    const float bro = b_ro[jo];

    // ---- initial hidden state (replicated) ----
    float hv0 = h0[0], hv1 = h0[1], hv2 = h0[2], hv3 = h0[3];
    float hown = h0[j];

    // ---- cooperative-load index precompute ----
    // input tile: 32 batches x 12 uint4 (48 floats) = 384 uint4, 3 per thread
    int  ibl[3], iq[3];
    size_t ibase[3];
#pragma unroll
    for (int k = 0; k < 3; k++) {
        int idx = tid + k * THR;
        ibl[k] = idx / 12;
        iq[k]  = idx % 12;
        // uint4 index of batch row start: (b*S)*3/4 = b*1536
        ibase[k] = (size_t)(blockIdx.x * BPC + ibl[k]) * (Sq * Iq / 4);
    }
    // output tile: 32 batches x 8 uint4 = 256 uint4, 2 per thread
    int obl[2], oq[2];
    size_t obase[2];
#pragma unroll
    for (int k = 0; k < 2; k++) {
        int idx = tid + k * THR;
        obl[k] = idx / 8;
        oq[k]  = idx % 8;
        obase[k] = (size_t)(blockIdx.x * BPC + obl[k]) * (Sq * Oq / 4);
    }

    const uint4* __restrict__ gin = reinterpret_cast<const uint4*>(inputs);
    uint4* __restrict__ gout = reinterpret_cast<uint4*>(out);

    // prologue: prefetch tile 0
    uint4 pf[3];
#pragma unroll
    for (int k = 0; k < 3; k++) pf[k] = gin[ibase[k] + iq[k]];

    for (int t = 0; t < NTILE; t++) {
        // stage prefetched inputs into smem
#pragma unroll
        for (int k = 0; k < 3; k++) {
            *reinterpret_cast<uint4*>(&s_in[ibl[k] * SIN_STRIDE + iq[k] * 4]) = pf[k];
        }
        // prefetch next tile (lands during compute)
        if (t + 1 < NTILE) {
#pragma unroll
            for (int k = 0; k < 3; k++)
                pf[k] = gin[ibase[k] + (size_t)(t + 1) * 12 + iq[k]];
        }
        __syncthreads();

        // ---- 16 recurrence steps ----
        const float* xin = &s_in[bloc * SIN_STRIDE];
        float* xout = &s_out[bloc * SOUT_STRIDE];
#pragma unroll
        for (int st = 0; st < TILE; st++) {
            const float x0 = xin[st * 3 + 0];
            const float x1 = xin[st * 3 + 1];
            const float x2 = xin[st * 3 + 2];

            // x-projections (independent of h — fill shfl latency)
            float ar = fmaf(wx[0][0], x0, fmaf(wx[0][1], x1, fmaf(wx[0][2], x2, br)));
            float az = fmaf(wx[1][0], x0, fmaf(wx[1][1], x1, fmaf(wx[1][2], x2, bz)));
            float an = fmaf(wx[2][0], x0, fmaf(wx[2][1], x1, fmaf(wx[2][2], x2, bxn)));

            // h-projections (tree-shaped dots)
            float hr = fmaf(wh[0][0], hv0, wh[0][1] * hv1) + fmaf(wh[0][2], hv2, wh[0][3] * hv3);
            float hz = fmaf(wh[1][0], hv0, wh[1][1] * hv1) + fmaf(wh[1][2], hv2, wh[1][3] * hv3);
            float hn = fmaf(wh[2][0], hv0, fmaf(wh[2][1], hv1, bhn)) + fmaf(wh[2][2], hv2, wh[2][3] * hv3);
            ar += hr;
            az += hz;

            const float r = sigmoid_fast(ar);
            const float z = sigmoid_fast(az);
            const float n = tanh_fast(fmaf(r, hn, an));
            const float hnew = fmaf(z, hown - n, n);

            // broadcast new hidden vector across the 4-thread group
            hv0 = __shfl_sync(0xffffffffu, hnew, gbase + 0);
            hv1 = __shfl_sync(0xffffffffu, hnew, gbase + 1);
            hv2 = __shfl_sync(0xffffffffu, hnew, gbase + 2);
            hv3 = __shfl_sync(0xffffffffu, hnew, gbase + 3);
            hown = hnew;

            // readout (threads j=0,1 write the two output channels)
            const float o = fmaf(wro[0], hv0, fmaf(wro[1], hv1,
                             fmaf(wro[2], hv2, fmaf(wro[3], hv3, bro))));
            if (j < 2) xout[st * 2 + j] = o;
        }
        __syncthreads();

        // ---- coalesced output store ----
#pragma unroll
        for (int k = 0; k < 2; k++) {
            uint4 v = *reinterpret_cast<const uint4*>(&s_out[obl[k] * SOUT_STRIDE + oq[k] * 4]);
            gout[obase[k] + (size_t)t * 8 + oq[k]] = v;
        }
        // next iteration's STS into s_in is safe: compute of this tile finished
        // before the sync above; the output STG reads s_out before each thread's
        // next compute phase, which is ordered by the sync at the top.
        __syncthreads();
    }

    // final hidden state
    if (write_hfinal) {
        out[(size_t)Bq * Sq * Oq + (size_t)b * Hq + j] = hown;
    }
}

extern "C" void kernel_launch(void* const* d_in, const int* in_sizes, int n_in,
                              void* d_out, int out_size) {
    const float* inputs = (const float*)d_in[0];
    const float* W_ih   = (const float*)d_in[1];
    const float* W_hh   = (const float*)d_in[2];
    const float* b_ih   = (const float*)d_in[3];
    const float* b_hh   = (const float*)d_in[4];
    const float* W_ro   = (const float*)d_in[5];
    const float* b_ro   = (const float*)d_in[6];
    const float* h0     = (const float*)d_in[7];
    float* out = (float*)d_out;

    const long long need = (long long)Bq * Sq * Oq + (long long)Bq * Hq;
    int write_hfinal = ((long long)out_size >= need) ? 1 : 0;

    gru_kernel<<<Bq / BPC, THR>>>(inputs, W_ih, W_hh, b_ih, b_hh,
                                  W_ro, b_ro, h0, out, write_hfinal);
}

// round 9
// speedup vs baseline: 1.0017x; 1.0017x over previous
#include <cuda_runtime.h>
#include <cstdint>

// TinyGRU: B=4096 sequences, S=2048 steps, I=3, H=4, O=2.
// Strategy: 4 threads per batch (one per hidden unit). Each thread computes
// the r/z/n gates of its unit; the full hidden vector is replicated across
// the 4 threads via shfl after every step. Inputs/outputs staged through
// shared memory in 16-step tiles for coalesced global traffic.

#define Bq   4096
#define Sq   2048
#define Iq   3
#define Hq   4
#define Oq   2
#define TILE 16
#define BPC  32          // batches per CTA
#define THR  128         // threads per CTA (4 per batch)
#define NTILE (Sq / TILE)

#define SIN_STRIDE  52   // 48 floats data + pad (bank-conflict free, 16B aligned rows)
#define SOUT_STRIDE 36   // 32 floats data + pad

__device__ __forceinline__ float ex2f(float x) {
    float y; asm("ex2.approx.f32 %0, %1;" : "=f"(y) : "f"(x)); return y;
}
__device__ __forceinline__ float rcpf(float x) {
    float y; asm("rcp.approx.f32 %0, %1;" : "=f"(y) : "f"(x)); return y;
}
// sigmoid(x) = 1 / (1 + exp(-x)) = 1 / (1 + 2^(-x*log2e))
__device__ __forceinline__ float sigmoid_fast(float x) {
    return rcpf(fmaf(0.0f, x, 1.0f) + ex2f(-1.4426950408889634f * x));
}
// tanh(x) = 2*sigmoid(2x) - 1
__device__ __forceinline__ float tanh_fast(float x) {
    return fmaf(2.0f, rcpf(1.0f + ex2f(-2.8853900817779268f * x)), -1.0f);
}

__global__ void __launch_bounds__(THR, 1) gru_kernel(
    const float* __restrict__ inputs,  // [B, S, I]
    const float* __restrict__ W_ih,    // [3H, I]
    const float* __restrict__ W_hh,    // [3H, H]
    const float* __restrict__ b_ih,    // [3H]
    const float* __restrict__ b_hh,    // [3H]
    const float* __restrict__ W_ro,    // [O, H]
    const float* __restrict__ b_ro,    // [O]
    const float* __restrict__ h0,      // [1, H]
    float* __restrict__ out,           // [B*S*O] (+ optional [B*H] h_final)
    int write_hfinal)
{
    __shared__ float s_in[BPC * SIN_STRIDE];
    __shared__ float s_out[BPC * SOUT_STRIDE];

    const int tid  = threadIdx.x;
    const int lane = tid & 31;
    const int j    = tid & 3;         // hidden unit owned by this thread
    const int bloc = tid >> 2;        // local batch 0..31
    const int b    = blockIdx.x * BPC + bloc;
    const unsigned gbase = (unsigned)(lane & ~3);

    // ---- load weights into registers (rows [r, z, n] = [0:H, H:2H, 2H:3H]) ----
    float wx[3][3], wh[3][4];
#pragma unroll
    for (int g = 0; g < 3; g++) {
        const int row = g * Hq + j;
#pragma unroll
        for (int i = 0; i < 3; i++) wx[g][i] = W_ih[row * Iq + i];
#pragma unroll
        for (int m = 0; m < 4; m++) wh[g][m] = W_hh[row * Hq + m];
    }
    const float br  = b_ih[j]          + b_hh[j];
    const float bz  = b_ih[Hq + j]     + b_hh[Hq + j];
    const float bxn = b_ih[2 * Hq + j];
    const float bhn = b_hh[2 * Hq + j];
    const int jo = (j < 2) ? j : 0;
    float wro[4];
#pragma unroll
    for (int m = 0; m < 4; m++) wro[m] = W_ro[jo * Hq + m];
    const float bro = b_ro[jo];

    // ---- initial hidden state (replicated) ----
    float hv0 = h0[0], hv1 = h0[1], hv2 = h0[2], hv3 = h0[3];
    float hown = h0[j];

    // ---- cooperative-load index precompute ----
    // input tile: 32 batches x 12 uint4 (48 floats) = 384 uint4, 3 per thread
    int  ibl[3], iq[3];
    size_t ibase[3];
#pragma unroll
    for (int k = 0; k < 3; k++) {
        int idx = tid + k * THR;
        ibl[k] = idx / 12;
        iq[k]  = idx % 12;
        // uint4 index of batch row start: (b*S)*3/4 = b*1536
        ibase[k] = (size_t)(blockIdx.x * BPC + ibl[k]) * (Sq * Iq / 4);
    }
    // output tile: 32 batches x 8 uint4 = 256 uint4, 2 per thread
    int obl[2], oq[2];
    size_t obase[2];
#pragma unroll
    for (int k = 0; k < 2; k++) {
        int idx = tid + k * THR;
        obl[k] = idx / 8;
        oq[k]  = idx % 8;
        obase[k] = (size_t)(blockIdx.x * BPC + obl[k]) * (Sq * Oq / 4);
    }

    const uint4* __restrict__ gin = reinterpret_cast<const uint4*>(inputs);
    uint4* __restrict__ gout = reinterpret_cast<uint4*>(out);

    // prologue: prefetch tile 0
    uint4 pf[3];
#pragma unroll
    for (int k = 0; k < 3; k++) pf[k] = gin[ibase[k] + iq[k]];

    for (int t = 0; t < NTILE; t++) {
        // stage prefetched inputs into smem
#pragma unroll
        for (int k = 0; k < 3; k++) {
            *reinterpret_cast<uint4*>(&s_in[ibl[k] * SIN_STRIDE + iq[k] * 4]) = pf[k];
        }
        // prefetch next tile (lands during compute)
        if (t + 1 < NTILE) {
#pragma unroll
            for (int k = 0; k < 3; k++)
                pf[k] = gin[ibase[k] + (size_t)(t + 1) * 12 + iq[k]];
        }
        __syncthreads();

        // ---- 16 recurrence steps ----
        const float* xin = &s_in[bloc * SIN_STRIDE];
        float* xout = &s_out[bloc * SOUT_STRIDE];
#pragma unroll
        for (int st = 0; st < TILE; st++) {
            const float x0 = xin[st * 3 + 0];
            const float x1 = xin[st * 3 + 1];
            const float x2 = xin[st * 3 + 2];

            // x-projections (independent of h — fill shfl latency)
            float ar = fmaf(wx[0][0], x0, fmaf(wx[0][1], x1, fmaf(wx[0][2], x2, br)));
            float az = fmaf(wx[1][0], x0, fmaf(wx[1][1], x1, fmaf(wx[1][2], x2, bz)));
            float an = fmaf(wx[2][0], x0, fmaf(wx[2][1], x1, fmaf(wx[2][2], x2, bxn)));

            // h-projections (tree-shaped dots)
            float hr = fmaf(wh[0][0], hv0, wh[0][1] * hv1) + fmaf(wh[0][2], hv2, wh[0][3] * hv3);
            float hz = fmaf(wh[1][0], hv0, wh[1][1] * hv1) + fmaf(wh[1][2], hv2, wh[1][3] * hv3);
            float hn = fmaf(wh[2][0], hv0, fmaf(wh[2][1], hv1, bhn)) + fmaf(wh[2][2], hv2, wh[2][3] * hv3);
            ar += hr;
            az += hz;

            const float r = sigmoid_fast(ar);
            const float z = sigmoid_fast(az);
            const float n = tanh_fast(fmaf(r, hn, an));
            const float hnew = fmaf(z, hown - n, n);

            // broadcast new hidden vector across the 4-thread group
            hv0 = __shfl_sync(0xffffffffu, hnew, gbase + 0);
            hv1 = __shfl_sync(0xffffffffu, hnew, gbase + 1);
            hv2 = __shfl_sync(0xffffffffu, hnew, gbase + 2);
            hv3 = __shfl_sync(0xffffffffu, hnew, gbase + 3);
            hown = hnew;

            // readout (threads j=0,1 write the two output channels)
            const float o = fmaf(wro[0], hv0, fmaf(wro[1], hv1,
                             fmaf(wro[2], hv2, fmaf(wro[3], hv3, bro))));
            if (j < 2) xout[st * 2 + j] = o;
        }
        __syncthreads();

        // ---- coalesced output store ----
#pragma unroll
        for (int k = 0; k < 2; k++) {
            uint4 v = *reinterpret_cast<const uint4*>(&s_out[obl[k] * SOUT_STRIDE + oq[k] * 4]);
            gout[obase[k] + (size_t)t * 8 + oq[k]] = v;
        }
        // next iteration's STS into s_in is safe: compute of this tile finished
        // before the sync above; the output STG reads s_out before each thread's
        // next compute phase, which is ordered by the sync at the top.
        __syncthreads();
    }

    // final hidden state
    if (write_hfinal) {
        out[(size_t)Bq * Sq * Oq + (size_t)b * Hq + j] = hown;
    }
}

extern "C" void kernel_launch(void* const* d_in, const int* in_sizes, int n_in,
                              void* d_out, int out_size) {
    const float* inputs = (const float*)d_in[0];
    const float* W_ih   = (const float*)d_in[1];
    const float* W_hh   = (const float*)d_in[2];
    const float* b_ih   = (const float*)d_in[3];
    const float* b_hh   = (const float*)d_in[4];
    const float* W_ro   = (const float*)d_in[5];
    const float* b_ro   = (const float*)d_in[6];
    const float* h0     = (const float*)d_in[7];
    float* out = (float*)d_out;

    const long long need = (long long)Bq * Sq * Oq + (long long)Bq * Hq;
    int write_hfinal = ((long long)out_size >= need) ? 1 : 0;

    gru_kernel<<<Bq / BPC, THR>>>(inputs, W_ih, W_hh, b_ih, b_hh,
                                  W_ro, b_ro, h0, out, write_hfinal);
}

// round 10
// speedup vs baseline: 1.0044x; 1.0027x over previous
#include <cuda_runtime.h>
#include <cstdint>

// TinyGRU: B=4096 sequences, S=2048 steps, I=3, H=4, O=2.
// Strategy: 4 threads per batch (one per hidden unit). Each thread computes
// the r/z/n gates of its unit; the full hidden vector is replicated across
// the 4 threads via shfl after every step. Inputs/outputs staged through
// shared memory in 16-step tiles for coalesced global traffic.

#define Bq   4096
#define Sq   2048
#define Iq   3
#define Hq   4
#define Oq   2
#define TILE 16
#define BPC  32          // batches per CTA
#define THR  128         // threads per CTA (4 per batch)
#define NTILE (Sq / TILE)

#define SIN_STRIDE  52   // 48 floats data + pad (bank-conflict free, 16B aligned rows)
#define SOUT_STRIDE 36   // 32 floats data + pad

__device__ __forceinline__ float ex2f(float x) {
    float y; asm("ex2.approx.f32 %0, %1;" : "=f"(y) : "f"(x)); return y;
}
__device__ __forceinline__ float rcpf(float x) {
    float y; asm("rcp.approx.f32 %0, %1;" : "=f"(y) : "f"(x)); return y;
}
// sigmoid(x) = 1 / (1 + exp(-x)) = 1 / (1 + 2^(-x*log2e))
__device__ __forceinline__ float sigmoid_fast(float x) {
    return rcpf(fmaf(0.0f, x, 1.0f) + ex2f(-1.4426950408889634f * x));
}
// tanh(x) = 2*sigmoid(2x) - 1
__device__ __forceinline__ float tanh_fast(float x) {
    return fmaf(2.0f, rcpf(1.0f + ex2f(-2.8853900817779268f * x)), -1.0f);
}

__global__ void __launch_bounds__(THR, 1) gru_kernel(
    const float* __restrict__ inputs,  // [B, S, I]
    const float* __restrict__ W_ih,    // [3H, I]
    const float* __restrict__ W_hh,    // [3H, H]
    const float* __restrict__ b_ih,    // [3H]
    const float* __restrict__ b_hh,    // [3H]
    const float* __restrict__ W_ro,    // [O, H]
    const float* __restrict__ b_ro,    // [O]
    const float* __restrict__ h0,      // [1, H]
    float* __restrict__ out,           // [B*S*O] (+ optional [B*H] h_final)
    int write_hfinal)
{
    __shared__ float s_in[BPC * SIN_STRIDE];
    __shared__ float s_out[BPC * SOUT_STRIDE];

    const int tid  = threadIdx.x;
    const int lane = tid & 31;
    const int j    = tid & 3;         // hidden unit owned by this thread
    const int bloc = tid >> 2;        // local batch 0..31
    const int b    = blockIdx.x * BPC + bloc;
    const unsigned gbase = (unsigned)(lane & ~3);

    // ---- load weights into registers (rows [r, z, n] = [0:H, H:2H, 2H:3H]) ----
    float wx[3][3], wh[3][4];
#pragma unroll
    for (int g = 0; g < 3; g++) {
        const int row = g * Hq + j;
#pragma unroll
        for (int i = 0; i < 3; i++) wx[g][i] = W_ih[row * Iq + i];
#pragma unroll
        for (int m = 0; m < 4; m++) wh[g][m] = W_hh[row * Hq + m];
    }
    const float br  = b_ih[j]          + b_hh[j];
    const float bz  = b_ih[Hq + j]     + b_hh[Hq + j];
    const float bxn = b_ih[2 * Hq + j];
    const float bhn = b_hh[2 * Hq + j];
    const int jo = (j < 2) ? j : 0;
    float wro[4];
#pragma unroll
    for (int m = 0; m < 4; m++) wro[m] = W_ro[jo * Hq + m];
    const float bro = b_ro[jo];

    // ---- initial hidden state (replicated) ----
    float hv0 = h0[0], hv1 = h0[1], hv2 = h0[2], hv3 = h0[3];
    float hown = h0[j];

    // ---- cooperative-load index precompute ----
    // input tile: 32 batches x 12 uint4 (48 floats) = 384 uint4, 3 per thread
    int  ibl[3], iq[3];
    size_t ibase[3];
#pragma unroll
    for (int k = 0; k < 3; k++) {
        int idx = tid + k * THR;
        ibl[k] = idx / 12;
        iq[k]  = idx % 12;
        // uint4 index of batch row start: (b*S)*3/4 = b*1536
        ibase[k] = (size_t)(blockIdx.x * BPC + ibl[k]) * (Sq * Iq / 4);
    }
    // output tile: 32 batches x 8 uint4 = 256 uint4, 2 per thread
    int obl[2], oq[2];
    size_t obase[2];
#pragma unroll
    for (int k = 0; k < 2; k++) {
        int idx = tid + k * THR;
        obl[k] = idx / 8;
        oq[k]  = idx % 8;
        obase[k] = (size_t)(blockIdx.x * BPC + obl[k]) * (Sq * Oq / 4);
    }

    const uint4* __restrict__ gin = reinterpret_cast<const uint4*>(inputs);
    uint4* __restrict__ gout = reinterpret_cast<uint4*>(out);

    // prologue: prefetch tile 0
    uint4 pf[3];
#pragma unroll
    for (int k = 0; k < 3; k++) pf[k] = gin[ibase[k] + iq[k]];

    for (int t = 0; t < NTILE; t++) {
        // stage prefetched inputs into smem
#pragma unroll
        for (int k = 0; k < 3; k++) {
            *reinterpret_cast<uint4*>(&s_in[ibl[k] * SIN_STRIDE + iq[k] * 4]) = pf[k];
        }
        // prefetch next tile (lands during compute)
        if (t + 1 < NTILE) {
#pragma unroll
            for (int k = 0; k < 3; k++)
                pf[k] = gin[ibase[k] + (size_t)(t + 1) * 12 + iq[k]];
        }
        __syncthreads();

        // ---- 16 recurrence steps ----
        const float* xin = &s_in[bloc * SIN_STRIDE];
        float* xout = &s_out[bloc * SOUT_STRIDE];
#pragma unroll
        for (int st = 0; st < TILE; st++) {
            const float x0 = xin[st * 3 + 0];
            const float x1 = xin[st * 3 + 1];
            const float x2 = xin[st * 3 + 2];

            // x-projections (independent of h — fill shfl latency)
            float ar = fmaf(wx[0][0], x0, fmaf(wx[0][1], x1, fmaf(wx[0][2], x2, br)));
            float az = fmaf(wx[1][0], x0, fmaf(wx[1][1], x1, fmaf(wx[1][2], x2, bz)));
            float an = fmaf(wx[2][0], x0, fmaf(wx[2][1], x1, fmaf(wx[2][2], x2, bxn)));

            // h-projections (tree-shaped dots)
            float hr = fmaf(wh[0][0], hv0, wh[0][1] * hv1) + fmaf(wh[0][2], hv2, wh[0][3] * hv3);
            float hz = fmaf(wh[1][0], hv0, wh[1][1] * hv1) + fmaf(wh[1][2], hv2, wh[1][3] * hv3);
            float hn = fmaf(wh[2][0], hv0, fmaf(wh[2][1], hv1, bhn)) + fmaf(wh[2][2], hv2, wh[2][3] * hv3);
            ar += hr;
            az += hz;

            const float r = sigmoid_fast(ar);
            const float z = sigmoid_fast(az);
            const float n = tanh_fast(fmaf(r, hn, an));
            const float hnew = fmaf(z, hown - n, n);

            // broadcast new hidden vector across the 4-thread group
            hv0 = __shfl_sync(0xffffffffu, hnew, gbase + 0);
            hv1 = __shfl_sync(0xffffffffu, hnew, gbase + 1);
            hv2 = __shfl_sync(0xffffffffu, hnew, gbase + 2);
            hv3 = __shfl_sync(0xffffffffu, hnew, gbase + 3);
            hown = hnew;

            // readout (threads j=0,1 write the two output channels)
            const float o = fmaf(wro[0], hv0, fmaf(wro[1], hv1,
                             fmaf(wro[2], hv2, fmaf(wro[3], hv3, bro))));
            if (j < 2) xout[st * 2 + j] = o;
        }
        __syncthreads();

        // ---- coalesced output store ----
#pragma unroll
        for (int k = 0; k < 2; k++) {
            uint4 v = *reinterpret_cast<const uint4*>(&s_out[obl[k] * SOUT_STRIDE + oq[k] * 4]);
            gout[obase[k] + (size_t)t * 8 + oq[k]] = v;
        }
        // next iteration's STS into s_in is safe: compute of this tile finished
        // before the sync above; the output STG reads s_out before each thread's
        // next compute phase, which is ordered by the sync at the top.
        __syncthreads();
    }

    // final hidden state
    if (write_hfinal) {
        out[(size_t)Bq * Sq * Oq + (size_t)b * Hq + j] = hown;
    }
}

extern "C" void kernel_launch(void* const* d_in, const int* in_sizes, int n_in,
                              void* d_out, int out_size) {
    const float* inputs = (const float*)d_in[0];
    const float* W_ih   = (const float*)d_in[1];
    const float* W_hh   = (const float*)d_in[2];
    const float* b_ih   = (const float*)d_in[3];
    const float* b_hh   = (const float*)d_in[4];
    const float* W_ro   = (const float*)d_in[5];
    const float* b_ro   = (const float*)d_in[6];
    const float* h0     = (const float*)d_in[7];
    float* out = (float*)d_out;

    const long long need = (long long)Bq * Sq * Oq + (long long)Bq * Hq;
    int write_hfinal = ((long long)out_size >= need) ? 1 : 0;

    gru_kernel<<<Bq / BPC, THR>>>(inputs, W_ih, W_hh, b_ih, b_hh,
                                  W_ro, b_ro, h0, out, write_hfinal);
}